// round 1
// baseline (speedup 1.0000x reference)
#include <cuda_runtime.h>
#include <math.h>

#define NLAYERS 4
#define HID 64
#define NROWS 8192            // B*N = 2*4096
#define ROWS_PER_BLK 64
#define NBLK (NROWS / ROWS_PER_BLK)   // 128
#define HT_S 72               // padded stride for transposed tiles (mult of 4, dodges conflicts)
#define SK_S 68               // padded stride for k/v tiles in M-phase

// Scratch (no allocations allowed): activations + per-layer k^T v accumulators.
__device__ float g_h[NROWS * HID];
__device__ float g_q[NROWS * HID];
__device__ float g_wh[NROWS * HID];
__device__ float g_M[NLAYERS * 2 * HID * HID];   // per layer, per batch, 64x64

__device__ __forceinline__ float gelu_exact(float x) {
    return 0.5f * x * (1.0f + erff(x * 0.70710678118654752440f));
}

// ---------------------------------------------------------------------------
// lift: h = x @ lift_w + lift_b   ([8192,3] @ [3,64]); also zero all g_M.
// grid 2048 x 256
// ---------------------------------------------------------------------------
__global__ __launch_bounds__(256) void lift_kernel(
    const float* __restrict__ x, const float* __restrict__ lw,
    const float* __restrict__ lb)
{
    int idx = blockIdx.x * 256 + threadIdx.x;      // 0 .. 524287
    int row = idx >> 6;
    int c   = idx & 63;
    const float* xr = x + row * 3;
    float acc = lb[c];
    acc = fmaf(xr[0], lw[c],        acc);
    acc = fmaf(xr[1], lw[64 + c],   acc);
    acc = fmaf(xr[2], lw[128 + c],  acc);
    g_h[idx] = acc;
    if (idx < NLAYERS * 2 * HID * HID) g_M[idx] = 0.0f;
}

// ---------------------------------------------------------------------------
// layerA: for 64 rows, compute [q|k|v|wh] = h @ [qw|kw|vw|bw] + bias  (64x256 GEMM),
// write q, wh to global, then reduce partial M = k^T v in-block and atomicAdd.
// grid 128 x 256, dynamic smem = (64*HT_S + 64*256)*4 bytes.
// ---------------------------------------------------------------------------
__global__ __launch_bounds__(256) void layerA_kernel(
    const float* __restrict__ qw, const float* __restrict__ qb,
    const float* __restrict__ kw, const float* __restrict__ kb,
    const float* __restrict__ vw, const float* __restrict__ vb,
    const float* __restrict__ bw, const float* __restrict__ bb,
    int layer)
{
    extern __shared__ float sm[];
    float* ht = sm;                    // [64][HT_S] transposed h: ht[j][r]
    float* sw = sm + 64 * HT_S;        // [64][256]  concat weights: sw[j][m*64+c]

    int tid = threadIdx.x;
    int r0  = blockIdx.x * ROWS_PER_BLK;
    int batch = r0 >> 12;
    float* Mb = g_M + layer * (2 * HID * HID) + batch * (HID * HID);

    // ---- load h tile transposed ----
    #pragma unroll
    for (int qq = 0; qq < 4; qq++) {
        int t4 = tid + 256 * qq;               // 1024 float4s
        int row = t4 >> 4, jf = t4 & 15;
        float4 v = *(const float4*)(g_h + (r0 + row) * HID + 4 * jf);
        ht[(4 * jf + 0) * HT_S + row] = v.x;
        ht[(4 * jf + 1) * HT_S + row] = v.y;
        ht[(4 * jf + 2) * HT_S + row] = v.z;
        ht[(4 * jf + 3) * HT_S + row] = v.w;
    }
    // ---- load 4 weight matrices, concatenated along columns ----
    {
        const float* wp[4] = {qw, kw, vw, bw};
        #pragma unroll
        for (int m = 0; m < 4; m++) {
            #pragma unroll
            for (int qq = 0; qq < 4; qq++) {
                int f = tid + 256 * qq;        // 1024 float4s of one 64x64 matrix
                int j = f >> 4, cf = f & 15;
                float4 v = *(const float4*)(wp[m] + j * 64 + 4 * cf);
                *(float4*)(sw + j * 256 + m * 64 + 4 * cf) = v;
            }
        }
    }
    __syncthreads();

    // ---- 64x256 GEMM: 8x8 register tiles; thread (ry,cy): rows 8ry.., cols 8cy.. ----
    int cy = tid & 31, ry = tid >> 5;
    float acc[8][8];
    #pragma unroll
    for (int a = 0; a < 8; a++)
        #pragma unroll
        for (int b = 0; b < 8; b++) acc[a][b] = 0.0f;

    const float* htp = ht + 8 * ry;
    const float* swp = sw + 8 * cy;
    #pragma unroll 4
    for (int j = 0; j < 64; j++) {
        float4 h0 = *(const float4*)(htp + j * HT_S);
        float4 h1 = *(const float4*)(htp + j * HT_S + 4);
        float4 w0 = *(const float4*)(swp + j * 256);
        float4 w1 = *(const float4*)(swp + j * 256 + 4);
        float hh[8] = {h0.x, h0.y, h0.z, h0.w, h1.x, h1.y, h1.z, h1.w};
        float ww[8] = {w0.x, w0.y, w0.z, w0.w, w1.x, w1.y, w1.z, w1.w};
        #pragma unroll
        for (int a = 0; a < 8; a++)
            #pragma unroll
            for (int b = 0; b < 8; b++)
                acc[a][b] = fmaf(hh[a], ww[b], acc[a][b]);
    }

    // ---- add bias ----
    {
        int C0 = 8 * cy;
        const float* bp = (C0 < 64) ? qb : (C0 < 128) ? kb : (C0 < 192) ? vb : bb;
        int off = C0 & 63;
        #pragma unroll
        for (int b = 0; b < 8; b++) {
            float bv = bp[off + b];
            #pragma unroll
            for (int a = 0; a < 8; a++) acc[a][b] += bv;
        }
    }

    // ---- write q (cols 0..63) and wh (cols 192..255) to global ----
    if (cy < 8) {
        #pragma unroll
        for (int a = 0; a < 8; a++) {
            int row = r0 + 8 * ry + a;
            float4 v0 = make_float4(acc[a][0], acc[a][1], acc[a][2], acc[a][3]);
            float4 v1 = make_float4(acc[a][4], acc[a][5], acc[a][6], acc[a][7]);
            *(float4*)(g_q + row * HID + 8 * cy)     = v0;
            *(float4*)(g_q + row * HID + 8 * cy + 4) = v1;
        }
    } else if (cy >= 24) {
        int cb = 8 * cy - 192;
        #pragma unroll
        for (int a = 0; a < 8; a++) {
            int row = r0 + 8 * ry + a;
            float4 v0 = make_float4(acc[a][0], acc[a][1], acc[a][2], acc[a][3]);
            float4 v1 = make_float4(acc[a][4], acc[a][5], acc[a][6], acc[a][7]);
            *(float4*)(g_wh + row * HID + cb)     = v0;
            *(float4*)(g_wh + row * HID + cb + 4) = v1;
        }
    }

    __syncthreads();   // everyone done reading sw before we overwrite it with k/v

    float* sk = sw;                 // [64][SK_S]
    float* sv = sw + 64 * SK_S;     // [64][SK_S]
    if (cy >= 8 && cy < 16) {
        int jb = 8 * (cy - 8);
        #pragma unroll
        for (int a = 0; a < 8; a++)
            #pragma unroll
            for (int b = 0; b < 8; b++)
                sk[(8 * ry + a) * SK_S + jb + b] = acc[a][b];
    } else if (cy >= 16 && cy < 24) {
        int lb2 = 8 * (cy - 16);
        #pragma unroll
        for (int a = 0; a < 8; a++)
            #pragma unroll
            for (int b = 0; b < 8; b++)
                sv[(8 * ry + a) * SK_S + lb2 + b] = acc[a][b];
    }
    __syncthreads();

    // ---- partial M[j][l] = sum_r k[r][j]*v[r][l]; 16x16 threads, 4x4 tiles ----
    int txl = tid & 15, tyj = tid >> 4;
    float macc[4][4];
    #pragma unroll
    for (int a = 0; a < 4; a++)
        #pragma unroll
        for (int b = 0; b < 4; b++) macc[a][b] = 0.0f;

    #pragma unroll 4
    for (int r = 0; r < 64; r++) {
        float4 kv = *(const float4*)(sk + r * SK_S + 4 * tyj);
        float4 vv = *(const float4*)(sv + r * SK_S + 4 * txl);
        float ka[4] = {kv.x, kv.y, kv.z, kv.w};
        float va[4] = {vv.x, vv.y, vv.z, vv.w};
        #pragma unroll
        for (int a = 0; a < 4; a++)
            #pragma unroll
            for (int b = 0; b < 4; b++)
                macc[a][b] = fmaf(ka[a], va[b], macc[a][b]);
    }
    #pragma unroll
    for (int a = 0; a < 4; a++)
        #pragma unroll
        for (int b = 0; b < 4; b++)
            atomicAdd(&Mb[(4 * tyj + a) * HID + 4 * txl + b], macc[a][b]);
}

// ---------------------------------------------------------------------------
// layerB: h = gelu(wh + (q @ M) * scale / N).  grid 128 x 256.
// ---------------------------------------------------------------------------
__global__ __launch_bounds__(256) void layerB_kernel(int layer)
{
    __shared__ float qt[64 * HT_S];   // transposed q tile
    __shared__ float sM[64 * 64];

    int tid = threadIdx.x;
    int r0  = blockIdx.x * ROWS_PER_BLK;
    int batch = r0 >> 12;
    const float* Mb = g_M + layer * (2 * HID * HID) + batch * (HID * HID);

    #pragma unroll
    for (int qq = 0; qq < 4; qq++) {
        int f = tid + 256 * qq;       // 1024 float4s
        *(float4*)(sM + 4 * f) = *(const float4*)(Mb + 4 * f);
    }
    #pragma unroll
    for (int qq = 0; qq < 4; qq++) {
        int t4 = tid + 256 * qq;
        int row = t4 >> 4, jf = t4 & 15;
        float4 v = *(const float4*)(g_q + (r0 + row) * HID + 4 * jf);
        qt[(4 * jf + 0) * HT_S + row] = v.x;
        qt[(4 * jf + 1) * HT_S + row] = v.y;
        qt[(4 * jf + 2) * HT_S + row] = v.z;
        qt[(4 * jf + 3) * HT_S + row] = v.w;
    }
    __syncthreads();

    int txc = tid & 15, tyr = tid >> 4;   // 4 cols, 4 rows per thread
    float acc[4][4];
    #pragma unroll
    for (int a = 0; a < 4; a++)
        #pragma unroll
        for (int b = 0; b < 4; b++) acc[a][b] = 0.0f;

    const float* qp = qt + 4 * tyr;
    const float* mp = sM + 4 * txc;
    #pragma unroll 4
    for (int j = 0; j < 64; j++) {
        float4 qv = *(const float4*)(qp + j * HT_S);
        float4 mv = *(const float4*)(mp + j * 64);
        float qa[4] = {qv.x, qv.y, qv.z, qv.w};
        float ma[4] = {mv.x, mv.y, mv.z, mv.w};
        #pragma unroll
        for (int a = 0; a < 4; a++)
            #pragma unroll
            for (int b = 0; b < 4; b++)
                acc[a][b] = fmaf(qa[a], ma[b], acc[a][b]);
    }

    const float cM = 0.125f / 4096.0f;    // (1/sqrt(64)) / N
    #pragma unroll
    for (int a = 0; a < 4; a++) {
        int row = r0 + 4 * tyr + a;
        float4 w = *(const float4*)(g_wh + row * HID + 4 * txc);
        float4 o;
        o.x = gelu_exact(fmaf(cM, acc[a][0], w.x));
        o.y = gelu_exact(fmaf(cM, acc[a][1], w.y));
        o.z = gelu_exact(fmaf(cM, acc[a][2], w.z));
        o.w = gelu_exact(fmaf(cM, acc[a][3], w.w));
        *(float4*)(g_h + row * HID + 4 * txc) = o;
    }
}

// ---------------------------------------------------------------------------
// proj: out[row] = dot(h[row], proj_w) + proj_b. Warp per row. grid 1024 x 256.
// ---------------------------------------------------------------------------
__global__ __launch_bounds__(256) void proj_kernel(
    const float* __restrict__ pw, const float* __restrict__ pb,
    float* __restrict__ out)
{
    int tid = threadIdx.x;
    int lane = tid & 31, w = tid >> 5;
    int row = blockIdx.x * 8 + w;
    const float* hr = g_h + row * HID;
    float s = fmaf(hr[lane], pw[lane], hr[lane + 32] * pw[lane + 32]);
    #pragma unroll
    for (int o = 16; o; o >>= 1) s += __shfl_xor_sync(0xffffffffu, s, o);
    if (lane == 0) out[row] = s + pb[0];
}

// ---------------------------------------------------------------------------
extern "C" void kernel_launch(void* const* d_in, const int* in_sizes, int n_in,
                              void* d_out, int out_size)
{
    const float* x      = (const float*)d_in[0];
    const float* lift_w = (const float*)d_in[1];
    const float* lift_b = (const float*)d_in[2];
    const float* blk_w  = (const float*)d_in[3];
    const float* blk_b  = (const float*)d_in[4];
    const float* q_w    = (const float*)d_in[5];
    const float* q_b    = (const float*)d_in[6];
    const float* k_w    = (const float*)d_in[7];
    const float* k_b    = (const float*)d_in[8];
    const float* v_w    = (const float*)d_in[9];
    const float* v_b    = (const float*)d_in[10];
    const float* proj_w = (const float*)d_in[11];
    const float* proj_b = (const float*)d_in[12];
    float* out = (float*)d_out;

    const int smemA = (64 * HT_S + 64 * 256) * 4;   // 83968 B
    cudaFuncSetAttribute(layerA_kernel,
                         cudaFuncAttributeMaxDynamicSharedMemorySize, smemA);

    lift_kernel<<<2048, 256>>>(x, lift_w, lift_b);

    for (int i = 0; i < NLAYERS; i++) {
        layerA_kernel<<<NBLK, 256, smemA>>>(
            q_w + i * 4096, q_b + i * 64,
            k_w + i * 4096, k_b + i * 64,
            v_w + i * 4096, v_b + i * 64,
            blk_w + i * 4096, blk_b + i * 64,
            i);
        layerB_kernel<<<NBLK, 256>>>(i);
    }

    proj_kernel<<<1024, 256>>>(proj_w, proj_b, out);
}

// round 2
// speedup vs baseline: 1.0416x; 1.0416x over previous
#include <cuda_runtime.h>
#include <math.h>

#define NLAYERS 4
#define HID 64
#define NROWS 8192            // B*N = 2*4096
#define ROWS_PER_BLK 64
#define NBLK (NROWS / ROWS_PER_BLK)   // 128
#define DUP_S 132             // floats per j-row of duplicated (pair) arrays; 16B-aligned rows, dodges store conflicts

typedef unsigned long long ull;

// Scratch (no allocations allowed): activations + per-layer k^T v accumulators.
__device__ float g_h[NROWS * HID];
__device__ float g_q[NROWS * HID];
__device__ float g_wh[NROWS * HID];
__device__ float g_M[NLAYERS * 2 * HID * HID];   // per layer, per batch, 64x64

// ---- packed fp32x2 helpers (sm_103a FFMA2) ----
__device__ __forceinline__ void ffma2(ull& d, ull a, ull b) {
    asm("fma.rn.f32x2 %0, %1, %2, %0;" : "+l"(d) : "l"(a), "l"(b));
}
__device__ __forceinline__ void add2(ull& d, ull a) {
    asm("add.rn.f32x2 %0, %0, %1;" : "+l"(d) : "l"(a));
}
__device__ __forceinline__ ull pack2(float x, float y) {
    ull r; asm("mov.b64 %0, {%1,%2};" : "=l"(r) : "f"(x), "f"(y)); return r;
}
__device__ __forceinline__ float2 unpack2(ull p) {
    float2 r; asm("mov.b64 {%0,%1}, %2;" : "=f"(r.x), "=f"(r.y) : "l"(p)); return r;
}

__device__ __forceinline__ float gelu_exact(float x) {
    return 0.5f * x * (1.0f + erff(x * 0.70710678118654752440f));
}

// ---------------------------------------------------------------------------
// lift: h = x @ lift_w + lift_b   ([8192,3] @ [3,64]); also zero all g_M.
// ---------------------------------------------------------------------------
__global__ __launch_bounds__(256) void lift_kernel(
    const float* __restrict__ x, const float* __restrict__ lw,
    const float* __restrict__ lb)
{
    int idx = blockIdx.x * 256 + threadIdx.x;      // 0 .. 524287
    int row = idx >> 6;
    int c   = idx & 63;
    const float* xr = x + row * 3;
    float acc = lb[c];
    acc = fmaf(xr[0], lw[c],        acc);
    acc = fmaf(xr[1], lw[64 + c],   acc);
    acc = fmaf(xr[2], lw[128 + c],  acc);
    g_h[idx] = acc;
    if (idx < NLAYERS * 2 * HID * HID) g_M[idx] = 0.0f;
}

// ---------------------------------------------------------------------------
// layerA: [q|k|v|wh] = h @ [qw|kw|vw|bw] + bias for 64 rows (all FFMA2),
// write q,wh; reduce partial M = k^T v (FFMA2) and atomicAdd.
// Thread map: ry = warp (8 rows), cy = lane (col pair 2cy in each of 4 matrices).
// smem: hd = dup-transposed h [64 j][DUP_S], sw = concat weights [64 j][256].
// ---------------------------------------------------------------------------
__global__ __launch_bounds__(256) void layerA_kernel(
    const float* __restrict__ qw, const float* __restrict__ qb,
    const float* __restrict__ kw, const float* __restrict__ kb,
    const float* __restrict__ vw, const float* __restrict__ vb,
    const float* __restrict__ bw, const float* __restrict__ bb,
    int layer)
{
    extern __shared__ float sm[];
    float* hd = sm;                    // 64*DUP_S = 8448 floats (dup pairs, transposed)
    float* sw = sm + 64 * DUP_S;       // 64*256 floats

    int tid = threadIdx.x;
    int cy  = tid & 31;
    int ry  = tid >> 5;
    int r0  = blockIdx.x * ROWS_PER_BLK;
    int batch = r0 >> 12;
    float* Mb = g_M + layer * (2 * HID * HID) + batch * (HID * HID);

    // ---- load h tile, store transposed + duplicated: hd[j*DUP_S + 2r] = (h,h) ----
    #pragma unroll
    for (int it = 0; it < 16; it++) {
        int idx = tid + 256 * it;              // 4096 elements
        int r = idx >> 6, j = idx & 63;
        float v = g_h[(r0 + r) * HID + j];
        *(float2*)&hd[j * DUP_S + 2 * r] = make_float2(v, v);
    }
    // ---- 4 weight matrices concatenated along columns ----
    {
        const float* wp[4] = {qw, kw, vw, bw};
        #pragma unroll
        for (int m = 0; m < 4; m++) {
            #pragma unroll
            for (int it = 0; it < 4; it++) {
                int f = tid + 256 * it;        // 1024 float4s of one 64x64 matrix
                int j = f >> 4, cf = f & 15;
                float4 v = *(const float4*)(wp[m] + j * 64 + 4 * cf);
                *(float4*)(sw + j * 256 + m * 64 + 4 * cf) = v;
            }
        }
    }
    __syncthreads();

    // ---- GEMM: acc[a][g] = pair over cols (g*64+2cy, +1), rows 8ry+a ----
    ull acc[8][4];
    #pragma unroll
    for (int a = 0; a < 8; a++)
        #pragma unroll
        for (int g = 0; g < 4; g++) acc[a][g] = 0ull;

    const float* hp0 = hd + 16 * ry;
    const float* swp = sw + 2 * cy;
    #pragma unroll 4
    for (int j = 0; j < 64; j++) {
        const ulonglong2* hp = (const ulonglong2*)(hp0 + j * DUP_S);
        ulonglong2 h01 = hp[0], h23 = hp[1], h45 = hp[2], h67 = hp[3];
        ull hh[8] = {h01.x, h01.y, h23.x, h23.y, h45.x, h45.y, h67.x, h67.y};
        ull w0 = *(const ull*)(swp + j * 256);
        ull w1 = *(const ull*)(swp + j * 256 + 64);
        ull w2 = *(const ull*)(swp + j * 256 + 128);
        ull w3 = *(const ull*)(swp + j * 256 + 192);
        #pragma unroll
        for (int a = 0; a < 8; a++) {
            ffma2(acc[a][0], hh[a], w0);
            ffma2(acc[a][1], hh[a], w1);
            ffma2(acc[a][2], hh[a], w2);
            ffma2(acc[a][3], hh[a], w3);
        }
    }

    // ---- bias ----
    {
        float2 b0 = *(const float2*)(qb + 2 * cy);
        float2 b1 = *(const float2*)(kb + 2 * cy);
        float2 b2 = *(const float2*)(vb + 2 * cy);
        float2 b3 = *(const float2*)(bb + 2 * cy);
        ull p0 = pack2(b0.x, b0.y), p1 = pack2(b1.x, b1.y);
        ull p2 = pack2(b2.x, b2.y), p3 = pack2(b3.x, b3.y);
        #pragma unroll
        for (int a = 0; a < 8; a++) {
            add2(acc[a][0], p0); add2(acc[a][1], p1);
            add2(acc[a][2], p2); add2(acc[a][3], p3);
        }
    }

    // ---- write q and wh (coalesced STG.64 per warp-row) ----
    #pragma unroll
    for (int a = 0; a < 8; a++) {
        int row = r0 + 8 * ry + a;
        *(float2*)(g_q  + row * HID + 2 * cy) = unpack2(acc[a][0]);
        *(float2*)(g_wh + row * HID + 2 * cy) = unpack2(acc[a][3]);
    }

    __syncthreads();   // all warps done reading hd/sw before overwrite

    // ---- stage k (duplicated) and v into smem ----
    float* skd = hd;                 // [row][2j] dup pairs, stride DUP_S
    float* svs = sw;                 // [row][l],  stride 64
    #pragma unroll
    for (int a = 0; a < 8; a++) {
        int row = 8 * ry + a;
        float2 kp = unpack2(acc[a][1]);
        *(float2*)&skd[row * DUP_S + 4 * cy]     = make_float2(kp.x, kp.x);
        *(float2*)&skd[row * DUP_S + 4 * cy + 2] = make_float2(kp.y, kp.y);
        *(float2*)&svs[row * 64 + 2 * cy] = unpack2(acc[a][2]);
    }
    __syncthreads();

    // ---- M[j][l] partial = sum_r k[r][j]*v[r][l]; thread: 4 j's x 4 l's (2 pairs) ----
    int txl = tid & 15, tyj = tid >> 4;
    ull macc[4][2];
    #pragma unroll
    for (int a = 0; a < 4; a++) { macc[a][0] = 0ull; macc[a][1] = 0ull; }

    const float* skp = skd + 8 * tyj;
    const float* svp = svs + 4 * txl;
    #pragma unroll 4
    for (int r = 0; r < 64; r++) {
        const ulonglong2* kp = (const ulonglong2*)(skp + r * DUP_S);
        ulonglong2 k01 = kp[0], k23 = kp[1];
        ull kd[4] = {k01.x, k01.y, k23.x, k23.y};
        ull v01 = *(const ull*)(svp + r * 64);
        ull v23 = *(const ull*)(svp + r * 64 + 2);
        #pragma unroll
        for (int a = 0; a < 4; a++) {
            ffma2(macc[a][0], kd[a], v01);
            ffma2(macc[a][1], kd[a], v23);
        }
    }
    #pragma unroll
    for (int a = 0; a < 4; a++) {
        float2 m0 = unpack2(macc[a][0]);
        float2 m1 = unpack2(macc[a][1]);
        float* dst = Mb + (4 * tyj + a) * HID + 4 * txl;
        atomicAdd(dst + 0, m0.x);
        atomicAdd(dst + 1, m0.y);
        atomicAdd(dst + 2, m1.x);
        atomicAdd(dst + 3, m1.y);
    }
}

// ---------------------------------------------------------------------------
// layerB: h = gelu(wh + q @ (M*scale/N)).  acc initialized with wh; M pre-scaled.
// Thread map: ry = warp (8 rows), cy = lane (col pair 2cy). All FFMA2.
// smem: qd dup-transposed q [64 j][DUP_S] + sM [64][64] pre-scaled.
// ---------------------------------------------------------------------------
__global__ __launch_bounds__(256) void layerB_kernel(int layer)
{
    extern __shared__ float smB[];
    float* qd = smB;                  // 8448 floats
    float* sM = smB + 64 * DUP_S;     // 4096 floats

    int tid = threadIdx.x;
    int cy  = tid & 31;
    int ry  = tid >> 5;
    int r0  = blockIdx.x * ROWS_PER_BLK;
    int batch = r0 >> 12;
    const float* Mb = g_M + layer * (2 * HID * HID) + batch * (HID * HID);

    const float cM = 0.125f / 4096.0f;    // (1/sqrt(64)) / N
    #pragma unroll
    for (int it = 0; it < 4; it++) {
        int f = tid + 256 * it;           // 1024 float4s
        float4 v = *(const float4*)(Mb + 4 * f);
        v.x *= cM; v.y *= cM; v.z *= cM; v.w *= cM;
        *(float4*)(sM + 4 * f) = v;
    }
    #pragma unroll
    for (int it = 0; it < 16; it++) {
        int idx = tid + 256 * it;
        int r = idx >> 6, j = idx & 63;
        float v = g_q[(r0 + r) * HID + j];
        *(float2*)&qd[j * DUP_S + 2 * r] = make_float2(v, v);
    }
    __syncthreads();

    // init acc with wh
    ull acc[8];
    #pragma unroll
    for (int a = 0; a < 8; a++) {
        int row = r0 + 8 * ry + a;
        float2 w = *(const float2*)(g_wh + row * HID + 2 * cy);
        acc[a] = pack2(w.x, w.y);
    }

    const float* qp0 = qd + 16 * ry;
    const float* mp  = sM + 2 * cy;
    #pragma unroll 4
    for (int j = 0; j < 64; j++) {
        const ulonglong2* qp = (const ulonglong2*)(qp0 + j * DUP_S);
        ulonglong2 q01 = qp[0], q23 = qp[1], q45 = qp[2], q67 = qp[3];
        ull qq[8] = {q01.x, q01.y, q23.x, q23.y, q45.x, q45.y, q67.x, q67.y};
        ull m = *(const ull*)(mp + j * 64);
        #pragma unroll
        for (int a = 0; a < 8; a++) ffma2(acc[a], qq[a], m);
    }

    #pragma unroll
    for (int a = 0; a < 8; a++) {
        int row = r0 + 8 * ry + a;
        float2 r = unpack2(acc[a]);
        r.x = gelu_exact(r.x);
        r.y = gelu_exact(r.y);
        *(float2*)(g_h + row * HID + 2 * cy) = r;
    }
}

// ---------------------------------------------------------------------------
// proj: out[row] = dot(h[row], proj_w) + proj_b. Warp per row.
// ---------------------------------------------------------------------------
__global__ __launch_bounds__(256) void proj_kernel(
    const float* __restrict__ pw, const float* __restrict__ pb,
    float* __restrict__ out)
{
    int tid = threadIdx.x;
    int lane = tid & 31, w = tid >> 5;
    int row = blockIdx.x * 8 + w;
    const float* hr = g_h + row * HID;
    float s = fmaf(hr[lane], pw[lane], hr[lane + 32] * pw[lane + 32]);
    #pragma unroll
    for (int o = 16; o; o >>= 1) s += __shfl_xor_sync(0xffffffffu, s, o);
    if (lane == 0) out[row] = s + pb[0];
}

// ---------------------------------------------------------------------------
extern "C" void kernel_launch(void* const* d_in, const int* in_sizes, int n_in,
                              void* d_out, int out_size)
{
    const float* x      = (const float*)d_in[0];
    const float* lift_w = (const float*)d_in[1];
    const float* lift_b = (const float*)d_in[2];
    const float* blk_w  = (const float*)d_in[3];
    const float* blk_b  = (const float*)d_in[4];
    const float* q_w    = (const float*)d_in[5];
    const float* q_b    = (const float*)d_in[6];
    const float* k_w    = (const float*)d_in[7];
    const float* k_b    = (const float*)d_in[8];
    const float* v_w    = (const float*)d_in[9];
    const float* v_b    = (const float*)d_in[10];
    const float* proj_w = (const float*)d_in[11];
    const float* proj_b = (const float*)d_in[12];
    float* out = (float*)d_out;

    const int smemA = (64 * DUP_S + 64 * 256) * 4;   // 99328 B
    const int smemB = (64 * DUP_S + 64 * 64) * 4;    // 50176 B
    cudaFuncSetAttribute(layerA_kernel,
                         cudaFuncAttributeMaxDynamicSharedMemorySize, smemA);
    cudaFuncSetAttribute(layerB_kernel,
                         cudaFuncAttributeMaxDynamicSharedMemorySize, smemB);

    lift_kernel<<<2048, 256>>>(x, lift_w, lift_b);

    for (int i = 0; i < NLAYERS; i++) {
        layerA_kernel<<<NBLK, 256, smemA>>>(
            q_w + i * 4096, q_b + i * 64,
            k_w + i * 4096, k_b + i * 64,
            v_w + i * 4096, v_b + i * 64,
            blk_w + i * 4096, blk_b + i * 64,
            i);
        layerB_kernel<<<NBLK, 256, smemB>>>(i);
    }

    proj_kernel<<<1024, 256>>>(proj_w, proj_b, out);
}